// round 6
// baseline (speedup 1.0000x reference)
#include <cuda_runtime.h>

#define BB 4
#define LL 2048
#define DD 1024
#define HH 16
#define HDIM 64

// Scratch (allocation-free rule: __device__ globals). 4 x 32 MB.
__device__ float g_Q[BB*LL*DD];
__device__ float g_K[BB*LL*DD];
__device__ float g_V[BB*LL*DD];
__device__ float g_C[BB*LL*DD];

// ---------------------------------------------------------------------------
// SGEMM: C[M,N] = A[M,K] @ W[K,N] + bias[N]   (all row-major, dims % 128 == 0)
// 128x128 tile, BK=8, 256 threads, 8x8 per-thread micro-tile.
// ---------------------------------------------------------------------------
__global__ __launch_bounds__(256) void sgemm_bias_kernel(
    const float* __restrict__ A, const float* __restrict__ W,
    const float* __restrict__ bias, float* __restrict__ C,
    int M, int N, int K)
{
    const int BM = 128, BN = 128, BK = 8;
    __shared__ float As[BK][BM];   // A tile stored transposed
    __shared__ float Bs[BK][BN];

    int tid  = threadIdx.x;
    int row0 = blockIdx.y * BM;
    int col0 = blockIdx.x * BN;

    int arow = tid >> 1,  acol = (tid & 1) << 2;   // 128 rows x 8 cols via float4
    int brow = tid >> 5,  bcol = (tid & 31) << 2;  // 8 rows x 128 cols via float4
    int tx = tid & 15, ty = tid >> 4;

    float acc[8][8];
#pragma unroll
    for (int i = 0; i < 8; i++)
#pragma unroll
        for (int j = 0; j < 8; j++) acc[i][j] = 0.f;

    const float* Aptr = A + (long)(row0 + arow) * K + acol;
    const float* Wptr = W + (long)brow * N + col0 + bcol;

    for (int k0 = 0; k0 < K; k0 += BK) {
        float4 a = *(const float4*)(Aptr + k0);
        As[acol + 0][arow] = a.x;
        As[acol + 1][arow] = a.y;
        As[acol + 2][arow] = a.z;
        As[acol + 3][arow] = a.w;
        float4 b = *(const float4*)(Wptr + (long)k0 * N);
        *(float4*)&Bs[brow][bcol] = b;
        __syncthreads();
#pragma unroll
        for (int k = 0; k < BK; k++) {
            float ar[8], br[8];
            *(float4*)&ar[0] = *(const float4*)&As[k][ty * 8];
            *(float4*)&ar[4] = *(const float4*)&As[k][ty * 8 + 4];
            *(float4*)&br[0] = *(const float4*)&Bs[k][tx * 8];
            *(float4*)&br[4] = *(const float4*)&Bs[k][tx * 8 + 4];
#pragma unroll
            for (int i = 0; i < 8; i++)
#pragma unroll
                for (int j = 0; j < 8; j++)
                    acc[i][j] += ar[i] * br[j];
        }
        __syncthreads();
    }

#pragma unroll
    for (int i = 0; i < 8; i++) {
        int r = row0 + ty * 8 + i;
#pragma unroll
        for (int j = 0; j < 8; j += 4) {
            int c = col0 + tx * 8 + j;
            float4 o;
            o.x = acc[i][j]     + bias[c];
            o.y = acc[i][j + 1] + bias[c + 1];
            o.z = acc[i][j + 2] + bias[c + 2];
            o.w = acc[i][j + 3] + bias[c + 3];
            *(float4*)&C[(long)r * N + c] = o;
        }
    }
}

// ---------------------------------------------------------------------------
// Flash-style attention, fp32. One block = one (b,h) x 64-query tile.
// 256 threads as 16x16; each thread owns a 4x4 S / O micro-tile.
// Online softmax with shuffle reductions across the 16 tx-lanes of each row.
// Shared: Qs [64][68], KVs (K transposed [d][c], then V [kc][d]) [64][68],
//         Ps [64][68]   -> 52224 B dynamic smem.
// ---------------------------------------------------------------------------
#define TQ 64
#define TK 64
#define SPAD 68

__global__ __launch_bounds__(256) void attn_kernel(
    const float* __restrict__ Qp, const float* __restrict__ Kp,
    const float* __restrict__ Vp, const int* __restrict__ mask,
    float* __restrict__ Ctx)
{
    extern __shared__ float sm[];
    float* Qs  = sm;                 // [64][SPAD]
    float* KVs = sm + TQ * SPAD;     // K phase: [d][c]; V phase: [kc][d]
    float* Ps  = sm + 2 * TQ * SPAD; // [r][c]

    int tid = threadIdx.x;
    int tx = tid & 15, ty = tid >> 4;
    int bh = blockIdx.y;
    int b = bh / HH, h = bh % HH;
    int q0 = blockIdx.x * TQ;
    const float scale = 0.125f;  // 1/sqrt(64)

    const float* Qbase = Qp + ((long)(b * LL + q0)) * DD + h * HDIM;
    // Load Q tile
#pragma unroll
    for (int s = tid; s < TQ * 16; s += 256) {
        int r = s >> 4, d4 = (s & 15) << 2;
        *(float4*)&Qs[r * SPAD + d4] = *(const float4*)(Qbase + (long)r * DD + d4);
    }

    float mrow[4], lrow[4], Oacc[4][4];
#pragma unroll
    for (int i = 0; i < 4; i++) {
        mrow[i] = -1e30f; lrow[i] = 0.f;
#pragma unroll
        for (int j = 0; j < 4; j++) Oacc[i][j] = 0.f;
    }

    const float* Kb = Kp + ((long)(b * LL)) * DD + h * HDIM;
    const float* Vb = Vp + ((long)(b * LL)) * DD + h * HDIM;
    const int*   Mb = mask + (long)b * LL * LL + (long)q0 * LL;
    int qr0 = ty * 4;

    for (int kt = 0; kt < LL; kt += TK) {
        __syncthreads();  // previous iteration's consumers of KVs/Ps are done (also covers Q load)
        // Load K tile transposed: KVs[d][c] = K[kt+c][d]
#pragma unroll
        for (int s = tid; s < TK * 16; s += 256) {
            int c = s >> 4, d4 = (s & 15) << 2;
            float4 kv = *(const float4*)(Kb + (long)(kt + c) * DD + d4);
            KVs[(d4 + 0) * SPAD + c] = kv.x;
            KVs[(d4 + 1) * SPAD + c] = kv.y;
            KVs[(d4 + 2) * SPAD + c] = kv.z;
            KVs[(d4 + 3) * SPAD + c] = kv.w;
        }
        __syncthreads();

        // S = (Q K^T): thread covers rows qr0..qr0+3, cols tx*4..tx*4+3
        float s4[4][4];
#pragma unroll
        for (int i = 0; i < 4; i++)
#pragma unroll
            for (int j = 0; j < 4; j++) s4[i][j] = 0.f;

#pragma unroll
        for (int d = 0; d < HDIM; d += 4) {
            float qr[4][4], kb[4][4];
#pragma unroll
            for (int i = 0; i < 4; i++)
                *(float4*)qr[i] = *(const float4*)&Qs[(qr0 + i) * SPAD + d];
#pragma unroll
            for (int dd = 0; dd < 4; dd++)
                *(float4*)kb[dd] = *(const float4*)&KVs[(d + dd) * SPAD + tx * 4];
#pragma unroll
            for (int i = 0; i < 4; i++)
#pragma unroll
                for (int dd = 0; dd < 4; dd++)
#pragma unroll
                    for (int j = 0; j < 4; j++)
                        s4[i][j] += qr[i][dd] * kb[dd][j];
        }
        __syncthreads();  // all S reads of KVs done; safe to overwrite with V

        // Load V tile: KVs[kc][d]
#pragma unroll
        for (int s = tid; s < TK * 16; s += 256) {
            int c = s >> 4, d4 = (s & 15) << 2;
            *(float4*)&KVs[c * SPAD + d4] =
                *(const float4*)(Vb + (long)(kt + c) * DD + d4);
        }

        // Mask + online softmax (row reductions over the 16 tx lanes)
#pragma unroll
        for (int i = 0; i < 4; i++) {
            int qrow = qr0 + i;
            int4 mv = *(const int4*)(Mb + (long)qrow * LL + kt + tx * 4);
            float sv[4];
            sv[0] = (mv.x == 0) ? -1e30f : s4[i][0] * scale;
            sv[1] = (mv.y == 0) ? -1e30f : s4[i][1] * scale;
            sv[2] = (mv.z == 0) ? -1e30f : s4[i][2] * scale;
            sv[3] = (mv.w == 0) ? -1e30f : s4[i][3] * scale;
            float mx = fmaxf(fmaxf(sv[0], sv[1]), fmaxf(sv[2], sv[3]));
#pragma unroll
            for (int off = 8; off >= 1; off >>= 1)
                mx = fmaxf(mx, __shfl_xor_sync(0xffffffffu, mx, off));
            float mnew = fmaxf(mrow[i], mx);
            float corr = __expf(mrow[i] - mnew);
            mrow[i] = mnew;
            float ls = 0.f;
#pragma unroll
            for (int j = 0; j < 4; j++) {
                float p = __expf(sv[j] - mnew);
                Ps[qrow * SPAD + tx * 4 + j] = p;
                ls += p;
            }
#pragma unroll
            for (int off = 8; off >= 1; off >>= 1)
                ls += __shfl_xor_sync(0xffffffffu, ls, off);
            lrow[i] = lrow[i] * corr + ls;
#pragma unroll
            for (int j = 0; j < 4; j++) Oacc[i][j] *= corr;
        }
        __syncthreads();  // V and Ps ready

        // O += P @ V : thread covers rows qr0.., d-cols tx*4..
#pragma unroll
        for (int kk0 = 0; kk0 < TK; kk0 += 4) {
            float pv[4][4], vv[4][4];
#pragma unroll
            for (int i = 0; i < 4; i++)
                *(float4*)pv[i] = *(const float4*)&Ps[(qr0 + i) * SPAD + kk0];
#pragma unroll
            for (int kk = 0; kk < 4; kk++)
                *(float4*)vv[kk] = *(const float4*)&KVs[(kk0 + kk) * SPAD + tx * 4];
#pragma unroll
            for (int i = 0; i < 4; i++)
#pragma unroll
                for (int kk = 0; kk < 4; kk++)
#pragma unroll
                    for (int j = 0; j < 4; j++)
                        Oacc[i][j] += pv[i][kk] * vv[kk][j];
        }
    }

    // Normalize and store ctx in [B, L, H*HD] layout
    float* Ob = Ctx + ((long)(b * LL + q0)) * DD + h * HDIM;
#pragma unroll
    for (int i = 0; i < 4; i++) {
        float inv = 1.f / lrow[i];
        float4 o;
        o.x = Oacc[i][0] * inv;
        o.y = Oacc[i][1] * inv;
        o.z = Oacc[i][2] * inv;
        o.w = Oacc[i][3] * inv;
        *(float4*)(Ob + (long)(qr0 + i) * DD + tx * 4) = o;
    }
}

// ---------------------------------------------------------------------------
extern "C" void kernel_launch(void* const* d_in, const int* in_sizes, int n_in,
                              void* d_out, int out_size)
{
    const float* q    = (const float*)d_in[0];
    const float* k    = (const float*)d_in[1];
    const float* v    = (const float*)d_in[2];
    const int*   mask = (const int*)  d_in[3];
    const float* WQ   = (const float*)d_in[4];
    const float* bQ   = (const float*)d_in[5];
    const float* WK   = (const float*)d_in[6];
    const float* bK   = (const float*)d_in[7];
    const float* WV   = (const float*)d_in[8];
    const float* bV   = (const float*)d_in[9];
    const float* WO   = (const float*)d_in[10];
    const float* bO   = (const float*)d_in[11];
    float* out = (float*)d_out;

    float *gQ, *gK, *gV, *gC;
    cudaGetSymbolAddress((void**)&gQ, g_Q);
    cudaGetSymbolAddress((void**)&gK, g_K);
    cudaGetSymbolAddress((void**)&gV, g_V);
    cudaGetSymbolAddress((void**)&gC, g_C);

    const int M = BB * LL;  // 8192
    dim3 gg(DD / 128, M / 128);  // (8, 64)

    sgemm_bias_kernel<<<gg, 256>>>(q, WQ, bQ, gQ, M, DD, DD);
    sgemm_bias_kernel<<<gg, 256>>>(k, WK, bK, gK, M, DD, DD);
    sgemm_bias_kernel<<<gg, 256>>>(v, WV, bV, gV, M, DD, DD);

    static int smem_set = 0;
    if (!smem_set) {
        cudaFuncSetAttribute(attn_kernel,
                             cudaFuncAttributeMaxDynamicSharedMemorySize,
                             3 * TQ * SPAD * (int)sizeof(float));
        smem_set = 1;
    }
    attn_kernel<<<dim3(LL / TQ, BB * HH), 256, 3 * TQ * SPAD * sizeof(float)>>>(
        gQ, gK, gV, mask, gC);

    sgemm_bias_kernel<<<gg, 256>>>(gC, WO, bO, out, M, DD, DD);
}

// round 7
// speedup vs baseline: 1.2889x; 1.2889x over previous
#include <cuda_runtime.h>
#include <cstdint>

#define BB 4
#define LL 2048
#define DD 1024
#define HH 16
#define HDIM 64

// Scratch (allocation-free rule: __device__ globals). 4 x 32 MB.
__device__ float g_Q[BB*LL*DD];
__device__ float g_K[BB*LL*DD];
__device__ float g_V[BB*LL*DD];
__device__ float g_C[BB*LL*DD];

// ---------------------------------------------------------------------------
// TF32 tensor-core SGEMM: C[M,N] = A[M,K] @ W[K,N] + bias[N]  (row-major)
// 128x128x32 block tile, 256 threads = 8 warps in 2x4, warp tile 64x32.
// mma.sync.aligned.m16n8k8.row.col.f32.tf32.tf32.f32, inputs rounded RNA.
// ---------------------------------------------------------------------------
#define GBM 128
#define GBN 128
#define GBK 32
#define BMP 129   // pad -> conflict-free transposed A stores
#define BNP 132   // pad, keeps rows 16B-aligned for float4 stores

__device__ __forceinline__ uint32_t f2tf32(float x) {
    uint32_t u;
    asm("cvt.rna.tf32.f32 %0, %1;" : "=r"(u) : "f"(x));
    return u;
}

__global__ __launch_bounds__(256) void sgemm_tf32_kernel(
    const float* __restrict__ A, const float* __restrict__ W,
    const float* __restrict__ bias, float* __restrict__ C,
    int M, int N, int K)
{
    __shared__ uint32_t As[GBK][BMP];   // [k][m]
    __shared__ uint32_t Bs[GBK][BNP];   // [k][n]

    int tid  = threadIdx.x;
    int row0 = blockIdx.y * GBM;
    int col0 = blockIdx.x * GBN;

    int lane = tid & 31;
    int wid  = tid >> 5;
    int g    = lane >> 2;        // group id (0..7)
    int tg   = lane & 3;         // thread-in-group (0..3)
    int wm0  = (wid >> 2) * 64;  // warp m origin within tile
    int wn0  = (wid & 3) * 32;   // warp n origin within tile

    // loaders
    int arow = tid >> 3;         // 0..31  (+32*it)
    int acol = (tid & 7) << 2;   // 0..28
    int brow = tid >> 5;         // 0..7   (+8*it)
    int bcol = (tid & 31) << 2;  // 0..124

    float acc[4][4][4];
#pragma unroll
    for (int i = 0; i < 4; i++)
#pragma unroll
        for (int j = 0; j < 4; j++)
#pragma unroll
            for (int c = 0; c < 4; c++) acc[i][j][c] = 0.f;

    for (int k0 = 0; k0 < K; k0 += GBK) {
        __syncthreads();
        // A tile -> As[k][m] (transposed store, pad 129 => conflict-free)
#pragma unroll
        for (int it = 0; it < 4; it++) {
            int r = arow + 32 * it;
            float4 a = *(const float4*)(A + (long)(row0 + r) * K + k0 + acol);
            As[acol + 0][r] = f2tf32(a.x);
            As[acol + 1][r] = f2tf32(a.y);
            As[acol + 2][r] = f2tf32(a.z);
            As[acol + 3][r] = f2tf32(a.w);
        }
        // W tile -> Bs[k][n]
#pragma unroll
        for (int it = 0; it < 4; it++) {
            int r = brow + 8 * it;
            float4 b = *(const float4*)(W + (long)(k0 + r) * N + col0 + bcol);
            uint32_t t0 = f2tf32(b.x), t1 = f2tf32(b.y),
                     t2 = f2tf32(b.z), t3 = f2tf32(b.w);
            *(uint4*)&Bs[r][bcol] = make_uint4(t0, t1, t2, t3);
        }
        __syncthreads();

#pragma unroll
        for (int ks = 0; ks < GBK; ks += 8) {
            uint32_t af[4][4], bf[4][2];
#pragma unroll
            for (int i = 0; i < 4; i++) {
                int m = wm0 + 16 * i;
                af[i][0] = As[ks + tg    ][m + g    ];
                af[i][1] = As[ks + tg    ][m + g + 8];
                af[i][2] = As[ks + tg + 4][m + g    ];
                af[i][3] = As[ks + tg + 4][m + g + 8];
            }
#pragma unroll
            for (int j = 0; j < 4; j++) {
                int n = wn0 + 8 * j;
                bf[j][0] = Bs[ks + tg    ][n + g];
                bf[j][1] = Bs[ks + tg + 4][n + g];
            }
#pragma unroll
            for (int i = 0; i < 4; i++)
#pragma unroll
                for (int j = 0; j < 4; j++) {
                    asm volatile(
                        "mma.sync.aligned.m16n8k8.row.col.f32.tf32.tf32.f32 "
                        "{%0,%1,%2,%3}, {%4,%5,%6,%7}, {%8,%9}, {%0,%1,%2,%3};\n"
                        : "+f"(acc[i][j][0]), "+f"(acc[i][j][1]),
                          "+f"(acc[i][j][2]), "+f"(acc[i][j][3])
                        : "r"(af[i][0]), "r"(af[i][1]), "r"(af[i][2]), "r"(af[i][3]),
                          "r"(bf[j][0]), "r"(bf[j][1]));
                }
        }
    }

    // Epilogue: c0,c1 at (row g, cols 2tg,2tg+1); c2,c3 at row g+8.
#pragma unroll
    for (int i = 0; i < 4; i++) {
        int r = row0 + wm0 + 16 * i + g;
#pragma unroll
        for (int j = 0; j < 4; j++) {
            int c = col0 + wn0 + 8 * j + 2 * tg;
            float b0 = bias[c], b1 = bias[c + 1];
            float2 o0 = make_float2(acc[i][j][0] + b0, acc[i][j][1] + b1);
            float2 o1 = make_float2(acc[i][j][2] + b0, acc[i][j][3] + b1);
            *(float2*)&C[(long)r * N + c]       = o0;
            *(float2*)&C[(long)(r + 8) * N + c] = o1;
        }
    }
}

// ---------------------------------------------------------------------------
// Flash-style attention, fp32 (unchanged from passing R5 kernel).
// ---------------------------------------------------------------------------
#define TQ 64
#define TK 64
#define SPAD 68

__global__ __launch_bounds__(256) void attn_kernel(
    const float* __restrict__ Qp, const float* __restrict__ Kp,
    const float* __restrict__ Vp, const int* __restrict__ mask,
    float* __restrict__ Ctx)
{
    extern __shared__ float sm[];
    float* Qs  = sm;                 // [64][SPAD]
    float* KVs = sm + TQ * SPAD;     // K phase: [d][c]; V phase: [kc][d]
    float* Ps  = sm + 2 * TQ * SPAD; // [r][c]

    int tid = threadIdx.x;
    int tx = tid & 15, ty = tid >> 4;
    int bh = blockIdx.y;
    int b = bh / HH, h = bh % HH;
    int q0 = blockIdx.x * TQ;
    const float scale = 0.125f;  // 1/sqrt(64)

    const float* Qbase = Qp + ((long)(b * LL + q0)) * DD + h * HDIM;
#pragma unroll
    for (int s = tid; s < TQ * 16; s += 256) {
        int r = s >> 4, d4 = (s & 15) << 2;
        *(float4*)&Qs[r * SPAD + d4] = *(const float4*)(Qbase + (long)r * DD + d4);
    }

    float mrow[4], lrow[4], Oacc[4][4];
#pragma unroll
    for (int i = 0; i < 4; i++) {
        mrow[i] = -1e30f; lrow[i] = 0.f;
#pragma unroll
        for (int j = 0; j < 4; j++) Oacc[i][j] = 0.f;
    }

    const float* Kb = Kp + ((long)(b * LL)) * DD + h * HDIM;
    const float* Vb = Vp + ((long)(b * LL)) * DD + h * HDIM;
    const int*   Mb = mask + (long)b * LL * LL + (long)q0 * LL;
    int qr0 = ty * 4;

    for (int kt = 0; kt < LL; kt += TK) {
        __syncthreads();
#pragma unroll
        for (int s = tid; s < TK * 16; s += 256) {
            int c = s >> 4, d4 = (s & 15) << 2;
            float4 kv = *(const float4*)(Kb + (long)(kt + c) * DD + d4);
            KVs[(d4 + 0) * SPAD + c] = kv.x;
            KVs[(d4 + 1) * SPAD + c] = kv.y;
            KVs[(d4 + 2) * SPAD + c] = kv.z;
            KVs[(d4 + 3) * SPAD + c] = kv.w;
        }
        __syncthreads();

        float s4[4][4];
#pragma unroll
        for (int i = 0; i < 4; i++)
#pragma unroll
            for (int j = 0; j < 4; j++) s4[i][j] = 0.f;

#pragma unroll
        for (int d = 0; d < HDIM; d += 4) {
            float qr[4][4], kb[4][4];
#pragma unroll
            for (int i = 0; i < 4; i++)
                *(float4*)qr[i] = *(const float4*)&Qs[(qr0 + i) * SPAD + d];
#pragma unroll
            for (int dd = 0; dd < 4; dd++)
                *(float4*)kb[dd] = *(const float4*)&KVs[(d + dd) * SPAD + tx * 4];
#pragma unroll
            for (int i = 0; i < 4; i++)
#pragma unroll
                for (int dd = 0; dd < 4; dd++)
#pragma unroll
                    for (int j = 0; j < 4; j++)
                        s4[i][j] += qr[i][dd] * kb[dd][j];
        }
        __syncthreads();

#pragma unroll
        for (int s = tid; s < TK * 16; s += 256) {
            int c = s >> 4, d4 = (s & 15) << 2;
            *(float4*)&KVs[c * SPAD + d4] =
                *(const float4*)(Vb + (long)(kt + c) * DD + d4);
        }

#pragma unroll
        for (int i = 0; i < 4; i++) {
            int qrow = qr0 + i;
            int4 mv = *(const int4*)(Mb + (long)qrow * LL + kt + tx * 4);
            float sv[4];
            sv[0] = (mv.x == 0) ? -1e30f : s4[i][0] * scale;
            sv[1] = (mv.y == 0) ? -1e30f : s4[i][1] * scale;
            sv[2] = (mv.z == 0) ? -1e30f : s4[i][2] * scale;
            sv[3] = (mv.w == 0) ? -1e30f : s4[i][3] * scale;
            float mx = fmaxf(fmaxf(sv[0], sv[1]), fmaxf(sv[2], sv[3]));
#pragma unroll
            for (int off = 8; off >= 1; off >>= 1)
                mx = fmaxf(mx, __shfl_xor_sync(0xffffffffu, mx, off));
            float mnew = fmaxf(mrow[i], mx);
            float corr = __expf(mrow[i] - mnew);
            mrow[i] = mnew;
            float ls = 0.f;
#pragma unroll
            for (int j = 0; j < 4; j++) {
                float p = __expf(sv[j] - mnew);
                Ps[qrow * SPAD + tx * 4 + j] = p;
                ls += p;
            }
#pragma unroll
            for (int off = 8; off >= 1; off >>= 1)
                ls += __shfl_xor_sync(0xffffffffu, ls, off);
            lrow[i] = lrow[i] * corr + ls;
#pragma unroll
            for (int j = 0; j < 4; j++) Oacc[i][j] *= corr;
        }
        __syncthreads();

#pragma unroll
        for (int kk0 = 0; kk0 < TK; kk0 += 4) {
            float pv[4][4], vv[4][4];
#pragma unroll
            for (int i = 0; i < 4; i++)
                *(float4*)pv[i] = *(const float4*)&Ps[(qr0 + i) * SPAD + kk0];
#pragma unroll
            for (int kk = 0; kk < 4; kk++)
                *(float4*)vv[kk] = *(const float4*)&KVs[(kk0 + kk) * SPAD + tx * 4];
#pragma unroll
            for (int i = 0; i < 4; i++)
#pragma unroll
                for (int kk = 0; kk < 4; kk++)
#pragma unroll
                    for (int j = 0; j < 4; j++)
                        Oacc[i][j] += pv[i][kk] * vv[kk][j];
        }
    }

    float* Ob = Ctx + ((long)(b * LL + q0)) * DD + h * HDIM;
#pragma unroll
    for (int i = 0; i < 4; i++) {
        float inv = 1.f / lrow[i];
        float4 o;
        o.x = Oacc[i][0] * inv;
        o.y = Oacc[i][1] * inv;
        o.z = Oacc[i][2] * inv;
        o.w = Oacc[i][3] * inv;
        *(float4*)(Ob + (long)(qr0 + i) * DD + tx * 4) = o;
    }
}

// ---------------------------------------------------------------------------
extern "C" void kernel_launch(void* const* d_in, const int* in_sizes, int n_in,
                              void* d_out, int out_size)
{
    const float* q    = (const float*)d_in[0];
    const float* k    = (const float*)d_in[1];
    const float* v    = (const float*)d_in[2];
    const int*   mask = (const int*)  d_in[3];
    const float* WQ   = (const float*)d_in[4];
    const float* bQ   = (const float*)d_in[5];
    const float* WK   = (const float*)d_in[6];
    const float* bK   = (const float*)d_in[7];
    const float* WV   = (const float*)d_in[8];
    const float* bV   = (const float*)d_in[9];
    const float* WO   = (const float*)d_in[10];
    const float* bO   = (const float*)d_in[11];
    float* out = (float*)d_out;

    float *gQ, *gK, *gV, *gC;
    cudaGetSymbolAddress((void**)&gQ, g_Q);
    cudaGetSymbolAddress((void**)&gK, g_K);
    cudaGetSymbolAddress((void**)&gV, g_V);
    cudaGetSymbolAddress((void**)&gC, g_C);

    const int M = BB * LL;  // 8192
    dim3 gg(DD / GBN, M / GBM);  // (8, 64)

    sgemm_tf32_kernel<<<gg, 256>>>(q, WQ, bQ, gQ, M, DD, DD);
    sgemm_tf32_kernel<<<gg, 256>>>(k, WK, bK, gK, M, DD, DD);
    sgemm_tf32_kernel<<<gg, 256>>>(v, WV, bV, gV, M, DD, DD);

    static int smem_set = 0;
    if (!smem_set) {
        cudaFuncSetAttribute(attn_kernel,
                             cudaFuncAttributeMaxDynamicSharedMemorySize,
                             3 * TQ * SPAD * (int)sizeof(float));
        smem_set = 1;
    }
    attn_kernel<<<dim3(LL / TQ, BB * HH), 256, 3 * TQ * SPAD * sizeof(float)>>>(
        gQ, gK, gV, mask, gC);

    sgemm_tf32_kernel<<<gg, 256>>>(gC, WO, bO, out, M, DD, DD);
}

// round 9
// speedup vs baseline: 2.2618x; 1.7548x over previous
#include <cuda_runtime.h>
#include <cstdint>

#define BB 4
#define LL 2048
#define DD 1024
#define HH 16
#define HDIM 64

// Scratch (allocation-free rule: __device__ globals). 4 x 32 MB.
__device__ float g_Q[BB*LL*DD];
__device__ float g_K[BB*LL*DD];
__device__ float g_V[BB*LL*DD];
__device__ float g_C[BB*LL*DD];

__device__ __forceinline__ uint32_t f2tf32(float x) {
    uint32_t u;
    asm("cvt.rna.tf32.f32 %0, %1;" : "=r"(u) : "f"(x));
    return u;
}

__device__ __forceinline__ void mma_tf32(float* c,
    uint32_t a0, uint32_t a1, uint32_t a2, uint32_t a3,
    uint32_t b0, uint32_t b1)
{
    asm volatile(
        "mma.sync.aligned.m16n8k8.row.col.f32.tf32.tf32.f32 "
        "{%0,%1,%2,%3}, {%4,%5,%6,%7}, {%8,%9}, {%0,%1,%2,%3};\n"
        : "+f"(c[0]), "+f"(c[1]), "+f"(c[2]), "+f"(c[3])
        : "r"(a0), "r"(a1), "r"(a2), "r"(a3), "r"(b0), "r"(b1));
}

// ---------------------------------------------------------------------------
// TF32 tensor-core SGEMM (unchanged from R6, passing).
// ---------------------------------------------------------------------------
#define GBM 128
#define GBN 128
#define GBK 32
#define BMP 129
#define BNP 132

__global__ __launch_bounds__(256) void sgemm_tf32_kernel(
    const float* __restrict__ A, const float* __restrict__ W,
    const float* __restrict__ bias, float* __restrict__ C,
    int M, int N, int K)
{
    __shared__ uint32_t As[GBK][BMP];   // [k][m]
    __shared__ uint32_t Bs[GBK][BNP];   // [k][n]

    int tid  = threadIdx.x;
    int row0 = blockIdx.y * GBM;
    int col0 = blockIdx.x * GBN;

    int lane = tid & 31;
    int wid  = tid >> 5;
    int g    = lane >> 2;
    int tg   = lane & 3;
    int wm0  = (wid >> 2) * 64;
    int wn0  = (wid & 3) * 32;

    int arow = tid >> 3;
    int acol = (tid & 7) << 2;
    int brow = tid >> 5;
    int bcol = (tid & 31) << 2;

    float acc[4][4][4];
#pragma unroll
    for (int i = 0; i < 4; i++)
#pragma unroll
        for (int j = 0; j < 4; j++)
#pragma unroll
            for (int c = 0; c < 4; c++) acc[i][j][c] = 0.f;

    for (int k0 = 0; k0 < K; k0 += GBK) {
        __syncthreads();
#pragma unroll
        for (int it = 0; it < 4; it++) {
            int r = arow + 32 * it;
            float4 a = *(const float4*)(A + (long)(row0 + r) * K + k0 + acol);
            As[acol + 0][r] = f2tf32(a.x);
            As[acol + 1][r] = f2tf32(a.y);
            As[acol + 2][r] = f2tf32(a.z);
            As[acol + 3][r] = f2tf32(a.w);
        }
#pragma unroll
        for (int it = 0; it < 4; it++) {
            int r = brow + 8 * it;
            float4 b = *(const float4*)(W + (long)(k0 + r) * N + col0 + bcol);
            uint32_t t0 = f2tf32(b.x), t1 = f2tf32(b.y),
                     t2 = f2tf32(b.z), t3 = f2tf32(b.w);
            *(uint4*)&Bs[r][bcol] = make_uint4(t0, t1, t2, t3);
        }
        __syncthreads();

#pragma unroll
        for (int ks = 0; ks < GBK; ks += 8) {
            uint32_t af[4][4], bf[4][2];
#pragma unroll
            for (int i = 0; i < 4; i++) {
                int m = wm0 + 16 * i;
                af[i][0] = As[ks + tg    ][m + g    ];
                af[i][1] = As[ks + tg    ][m + g + 8];
                af[i][2] = As[ks + tg + 4][m + g    ];
                af[i][3] = As[ks + tg + 4][m + g + 8];
            }
#pragma unroll
            for (int j = 0; j < 4; j++) {
                int n = wn0 + 8 * j;
                bf[j][0] = Bs[ks + tg    ][n + g];
                bf[j][1] = Bs[ks + tg + 4][n + g];
            }
#pragma unroll
            for (int i = 0; i < 4; i++)
#pragma unroll
                for (int j = 0; j < 4; j++)
                    mma_tf32(acc[i][j], af[i][0], af[i][1], af[i][2], af[i][3],
                             bf[j][0], bf[j][1]);
        }
    }

#pragma unroll
    for (int i = 0; i < 4; i++) {
        int r = row0 + wm0 + 16 * i + g;
#pragma unroll
        for (int j = 0; j < 4; j++) {
            int c = col0 + wn0 + 8 * j + 2 * tg;
            float b0 = bias[c], b1 = bias[c + 1];
            float2 o0 = make_float2(acc[i][j][0] + b0, acc[i][j][1] + b1);
            float2 o1 = make_float2(acc[i][j][2] + b0, acc[i][j][3] + b1);
            *(float2*)&C[(long)r * N + c]       = o0;
            *(float2*)&C[(long)(r + 8) * N + c] = o1;
        }
    }
}

// ---------------------------------------------------------------------------
// TF32 tensor-core flash attention.
// One block = one (b,h) x 128-query tile. 256 threads = 8 warps;
// warp w owns S/O rows [16w, 16w+16). TK=64 key tile.
// S = Q@K^T via m16n8k8 (scale folded into Q), fp32 online softmax in regs,
// P written to smem as tf32 bits, O += P@V via m16n8k8.
// Mask tile is staged into the P smem region (1:1 thread ownership).
// ---------------------------------------------------------------------------
#define AQ 128
#define AK 64
#define QSTR 68
#define KSTR 68
#define VSTR 72
#define PSTR 68
#define ATT_SMEM ((AQ*QSTR + AK*KSTR + AK*VSTR + AQ*PSTR) * 4)

__global__ __launch_bounds__(256) void attn_tf32_kernel(
    const float* __restrict__ Qp, const float* __restrict__ Kp,
    const float* __restrict__ Vp, const int* __restrict__ mask,
    float* __restrict__ Ctx)
{
    extern __shared__ char smemraw[];
    uint32_t* Qs = (uint32_t*)smemraw;           // [AQ][QSTR] tf32
    uint32_t* Ks = Qs + AQ * QSTR;               // [AK][KSTR] tf32
    uint32_t* Vs = Ks + AK * KSTR;               // [AK][VSTR] tf32
    float*    Ps = (float*)(Vs + AK * VSTR);     // [AQ][PSTR] mask ints, then P tf32 bits
    uint32_t* Pu = (uint32_t*)Ps;

    int tid  = threadIdx.x;
    int lane = tid & 31, wid = tid >> 5;
    int g = lane >> 2, tg = lane & 3;
    int wm = wid * 16;
    int bh = blockIdx.y;
    int b = bh / HH, h = bh % HH;
    int q0 = blockIdx.x * AQ;

    int row0 = wm + g;       // this thread's S/O rows (local)
    int row1 = wm + g + 8;

    // Stage Q once (scale 0.125 folded in; exact, power of two)
    const float* Qbase = Qp + ((long)(b * LL + q0)) * DD + h * HDIM;
#pragma unroll
    for (int it = 0; it < 8; it++) {
        int s = tid + it * 256;
        int r = s >> 4, c4 = (s & 15) << 2;
        float4 qv = *(const float4*)(Qbase + (long)r * DD + c4);
        Qs[r * QSTR + c4 + 0] = f2tf32(qv.x * 0.125f);
        Qs[r * QSTR + c4 + 1] = f2tf32(qv.y * 0.125f);
        Qs[r * QSTR + c4 + 2] = f2tf32(qv.z * 0.125f);
        Qs[r * QSTR + c4 + 3] = f2tf32(qv.w * 0.125f);
    }

    float Of[8][4];
#pragma unroll
    for (int j = 0; j < 8; j++)
#pragma unroll
        for (int c = 0; c < 4; c++) Of[j][c] = 0.f;
    float m0 = -1e30f, m1 = -1e30f, l0 = 0.f, l1 = 0.f;

    const float* Kb = Kp + ((long)(b * LL)) * DD + h * HDIM;
    const float* Vb = Vp + ((long)(b * LL)) * DD + h * HDIM;
    const int*   Mb = mask + (long)b * LL * LL + (long)q0 * LL;

    for (int kt = 0; kt < LL; kt += AK) {
        __syncthreads();  // prev PV done reading Ps/Vs; prev S done reading Ks

        // Stage K [AK][KSTR] and V [AK][VSTR] (tf32)
#pragma unroll
        for (int it = 0; it < 4; it++) {
            int s = tid + it * 256;
            int r = s >> 4, c4 = (s & 15) << 2;
            float4 kv = *(const float4*)(Kb + (long)(kt + r) * DD + c4);
            Ks[r * KSTR + c4 + 0] = f2tf32(kv.x);
            Ks[r * KSTR + c4 + 1] = f2tf32(kv.y);
            Ks[r * KSTR + c4 + 2] = f2tf32(kv.z);
            Ks[r * KSTR + c4 + 3] = f2tf32(kv.w);
            float4 vv = *(const float4*)(Vb + (long)(kt + r) * DD + c4);
            Vs[r * VSTR + c4 + 0] = f2tf32(vv.x);
            Vs[r * VSTR + c4 + 1] = f2tf32(vv.y);
            Vs[r * VSTR + c4 + 2] = f2tf32(vv.z);
            Vs[r * VSTR + c4 + 3] = f2tf32(vv.w);
        }
        // Stage mask tile into Ps (raw int bits)
#pragma unroll
        for (int it = 0; it < 8; it++) {
            int s = tid + it * 256;
            int r = s >> 4, c4 = (s & 15) << 2;
            int4 mv = *(const int4*)(Mb + (long)r * LL + kt + c4);
            *(int4*)&Ps[r * PSTR + c4] = mv;
        }
        __syncthreads();

        // S = Q @ K^T  (warp: 16 rows x 64 keys)
        float sf[8][4];
#pragma unroll
        for (int j = 0; j < 8; j++)
#pragma unroll
            for (int c = 0; c < 4; c++) sf[j][c] = 0.f;

#pragma unroll
        for (int ks = 0; ks < AK; ks += 8) {
            uint32_t a0 = Qs[row0 * QSTR + ks + tg];
            uint32_t a1 = Qs[row1 * QSTR + ks + tg];
            uint32_t a2 = Qs[row0 * QSTR + ks + tg + 4];
            uint32_t a3 = Qs[row1 * QSTR + ks + tg + 4];
#pragma unroll
            for (int j = 0; j < 8; j++) {
                uint32_t b0 = Ks[(8 * j + g) * KSTR + ks + tg];
                uint32_t b1 = Ks[(8 * j + g) * KSTR + ks + tg + 4];
                mma_tf32(sf[j], a0, a1, a2, a3, b0, b1);
            }
        }

        // Mask + online softmax (rows fully warp-local; reduce over quad tg)
        float mx0 = -1e30f, mx1 = -1e30f;
#pragma unroll
        for (int j = 0; j < 8; j++) {
            int cb = 8 * j + 2 * tg;
            int2 mv0 = *(const int2*)&Ps[row0 * PSTR + cb];
            int2 mv1 = *(const int2*)&Ps[row1 * PSTR + cb];
            sf[j][0] = mv0.x ? sf[j][0] : -1e30f;
            sf[j][1] = mv0.y ? sf[j][1] : -1e30f;
            sf[j][2] = mv1.x ? sf[j][2] : -1e30f;
            sf[j][3] = mv1.y ? sf[j][3] : -1e30f;
            mx0 = fmaxf(mx0, fmaxf(sf[j][0], sf[j][1]));
            mx1 = fmaxf(mx1, fmaxf(sf[j][2], sf[j][3]));
        }
        mx0 = fmaxf(mx0, __shfl_xor_sync(0xffffffffu, mx0, 1));
        mx0 = fmaxf(mx0, __shfl_xor_sync(0xffffffffu, mx0, 2));
        mx1 = fmaxf(mx1, __shfl_xor_sync(0xffffffffu, mx1, 1));
        mx1 = fmaxf(mx1, __shfl_xor_sync(0xffffffffu, mx1, 2));

        float mn0 = fmaxf(m0, mx0), mn1 = fmaxf(m1, mx1);
        float cr0 = __expf(m0 - mn0), cr1 = __expf(m1 - mn1);
        m0 = mn0; m1 = mn1;

        float ls0 = 0.f, ls1 = 0.f;
#pragma unroll
        for (int j = 0; j < 8; j++) {
            float p0 = __expf(sf[j][0] - mn0);
            float p1 = __expf(sf[j][1] - mn0);
            float p2 = __expf(sf[j][2] - mn1);
            float p3 = __expf(sf[j][3] - mn1);
            ls0 += p0 + p1;
            ls1 += p2 + p3;
            int cb = 8 * j + 2 * tg;
            *(uint2*)&Pu[row0 * PSTR + cb] = make_uint2(f2tf32(p0), f2tf32(p1));
            *(uint2*)&Pu[row1 * PSTR + cb] = make_uint2(f2tf32(p2), f2tf32(p3));
        }
        ls0 += __shfl_xor_sync(0xffffffffu, ls0, 1);
        ls0 += __shfl_xor_sync(0xffffffffu, ls0, 2);
        ls1 += __shfl_xor_sync(0xffffffffu, ls1, 1);
        ls1 += __shfl_xor_sync(0xffffffffu, ls1, 2);
        l0 = l0 * cr0 + ls0;
        l1 = l1 * cr1 + ls1;
#pragma unroll
        for (int j = 0; j < 8; j++) {
            Of[j][0] *= cr0; Of[j][1] *= cr0;
            Of[j][2] *= cr1; Of[j][3] *= cr1;
        }
        __syncthreads();  // P (tf32) visible to whole warp set

        // O += P @ V
#pragma unroll
        for (int ks = 0; ks < AK; ks += 8) {
            uint32_t a0 = Pu[row0 * PSTR + ks + tg];
            uint32_t a1 = Pu[row1 * PSTR + ks + tg];
            uint32_t a2 = Pu[row0 * PSTR + ks + tg + 4];
            uint32_t a3 = Pu[row1 * PSTR + ks + tg + 4];
#pragma unroll
            for (int j = 0; j < 8; j++) {
                uint32_t b0 = Vs[(ks + tg)     * VSTR + 8 * j + g];
                uint32_t b1 = Vs[(ks + tg + 4) * VSTR + 8 * j + g];
                mma_tf32(Of[j], a0, a1, a2, a3, b0, b1);
            }
        }
    }

    // Normalize, store ctx [B, L, H*HD]
    float inv0 = 1.f / l0, inv1 = 1.f / l1;
    float* Ob = Ctx + ((long)(b * LL + q0)) * DD + h * HDIM;
#pragma unroll
    for (int j = 0; j < 8; j++) {
        int c = 8 * j + 2 * tg;
        *(float2*)&Ob[(long)row0 * DD + c] =
            make_float2(Of[j][0] * inv0, Of[j][1] * inv0);
        *(float2*)&Ob[(long)row1 * DD + c] =
            make_float2(Of[j][2] * inv1, Of[j][3] * inv1);
    }
}

// ---------------------------------------------------------------------------
extern "C" void kernel_launch(void* const* d_in, const int* in_sizes, int n_in,
                              void* d_out, int out_size)
{
    const float* q    = (const float*)d_in[0];
    const float* k    = (const float*)d_in[1];
    const float* v    = (const float*)d_in[2];
    const int*   mask = (const int*)  d_in[3];
    const float* WQ   = (const float*)d_in[4];
    const float* bQ   = (const float*)d_in[5];
    const float* WK   = (const float*)d_in[6];
    const float* bK   = (const float*)d_in[7];
    const float* WV   = (const float*)d_in[8];
    const float* bV   = (const float*)d_in[9];
    const float* WO   = (const float*)d_in[10];
    const float* bO   = (const float*)d_in[11];
    float* out = (float*)d_out;

    float *gQ, *gK, *gV, *gC;
    cudaGetSymbolAddress((void**)&gQ, g_Q);
    cudaGetSymbolAddress((void**)&gK, g_K);
    cudaGetSymbolAddress((void**)&gV, g_V);
    cudaGetSymbolAddress((void**)&gC, g_C);

    const int M = BB * LL;  // 8192
    dim3 gg(DD / GBN, M / GBM);  // (8, 64)

    sgemm_tf32_kernel<<<gg, 256>>>(q, WQ, bQ, gQ, M, DD, DD);
    sgemm_tf32_kernel<<<gg, 256>>>(k, WK, bK, gK, M, DD, DD);
    sgemm_tf32_kernel<<<gg, 256>>>(v, WV, bV, gV, M, DD, DD);

    static int smem_set = 0;
    if (!smem_set) {
        cudaFuncSetAttribute(attn_tf32_kernel,
                             cudaFuncAttributeMaxDynamicSharedMemorySize,
                             ATT_SMEM);
        smem_set = 1;
    }
    attn_tf32_kernel<<<dim3(LL / AQ, BB * HH), 256, ATT_SMEM>>>(
        gQ, gK, gV, mask, gC);

    sgemm_tf32_kernel<<<gg, 256>>>(gC, WO, bO, out, M, DD, DD);
}

// round 10
// speedup vs baseline: 3.1548x; 1.3948x over previous
#include <cuda_runtime.h>
#include <cstdint>

#define BB 4
#define LL 2048
#define DD 1024
#define HH 16
#define HDIM 64

// Scratch (allocation-free rule: __device__ globals). 4 x 32 MB.
__device__ float g_Q[BB*LL*DD];
__device__ float g_K[BB*LL*DD];
__device__ float g_V[BB*LL*DD];
__device__ float g_C[BB*LL*DD];

__device__ __forceinline__ uint32_t f2tf32(float x) {
    uint32_t u;
    asm("cvt.rna.tf32.f32 %0, %1;" : "=r"(u) : "f"(x));
    return u;
}

__device__ __forceinline__ void mma_tf32(float* c,
    uint32_t a0, uint32_t a1, uint32_t a2, uint32_t a3,
    uint32_t b0, uint32_t b1)
{
    asm volatile(
        "mma.sync.aligned.m16n8k8.row.col.f32.tf32.tf32.f32 "
        "{%0,%1,%2,%3}, {%4,%5,%6,%7}, {%8,%9}, {%0,%1,%2,%3};\n"
        : "+f"(c[0]), "+f"(c[1]), "+f"(c[2]), "+f"(c[3])
        : "r"(a0), "r"(a1), "r"(a2), "r"(a3), "r"(b0), "r"(b1));
}

__device__ __forceinline__ void cpasync16(uint32_t dst, const void* src) {
    asm volatile("cp.async.cg.shared.global [%0], [%1], 16;\n"
                 :: "r"(dst), "l"(src));
}
__device__ __forceinline__ void cp_commit() {
    asm volatile("cp.async.commit_group;\n" ::: "memory");
}
__device__ __forceinline__ void cp_wait1() {
    asm volatile("cp.async.wait_group 1;\n" ::: "memory");
}

// ---------------------------------------------------------------------------
// TF32 tensor-core GEMM with 2-stage cp.async pipeline.
// C[M,N] = A[M,K] @ W[K,N] + bias[N], 128x128x32 tile, 8 warps, 64x32/warp.
// Smem holds raw f32 (cp.async); cvt.rna.tf32 at fragment-load time
// (identical operand values as converting at staging -> same numerics).
// A: [2][128][AP=36]  (4g+tg bank bijection), B: [2][32][BP=136] (8tg+g).
// Grid z batches independent GEMMs (QKV in one launch).
// ---------------------------------------------------------------------------
#define GBM 128
#define GBN 128
#define GBK 32
#define AP 36
#define BP 136
#define GSMEM ((2*GBM*AP + 2*GBK*BP) * 4)   // 71680 B

struct GemmArgs {
    const float* A; const float* W; const float* bias; float* C;
};

__global__ __launch_bounds__(256) void sgemm_tf32_pipe_kernel(
    GemmArgs ga0, GemmArgs ga1, GemmArgs ga2, int M, int N, int K)
{
    extern __shared__ float smemf[];
    float* Asf = smemf;                 // [2][128][AP]
    float* Bsf = smemf + 2 * GBM * AP;  // [2][32][BP]

    GemmArgs ga = (blockIdx.z == 0) ? ga0 : (blockIdx.z == 1) ? ga1 : ga2;
    const float* __restrict__ A    = ga.A;
    const float* __restrict__ W    = ga.W;
    const float* __restrict__ bias = ga.bias;
    float* __restrict__ C          = ga.C;

    int tid  = threadIdx.x;
    int row0 = blockIdx.y * GBM;
    int col0 = blockIdx.x * GBN;

    int lane = tid & 31;
    int wid  = tid >> 5;
    int g    = lane >> 2;
    int tg   = lane & 3;
    int wm0  = (wid >> 2) * 64;
    int wn0  = (wid & 3) * 32;

    // staging coords
    int arow = tid >> 3;          // 0..31 (+32*it)
    int acol = (tid & 7) << 2;    // 0..28
    int brow = tid >> 5;          // 0..7  (+8*it)
    int bcol = (tid & 31) << 2;   // 0..124

    uint32_t aS = (uint32_t)__cvta_generic_to_shared(Asf);
    uint32_t bS = (uint32_t)__cvta_generic_to_shared(Bsf);

    const float* Abase = A + (long)(row0 + arow) * K + acol;
    const float* Wbase = W + (long)brow * N + col0 + bcol;

    float acc[4][4][4];
#pragma unroll
    for (int i = 0; i < 4; i++)
#pragma unroll
        for (int j = 0; j < 4; j++)
#pragma unroll
            for (int c = 0; c < 4; c++) acc[i][j][c] = 0.f;

    const int NIT = 1024 / GBK;  // K/GBK = 32

    // prologue: stage tile 0 into buf 0
    {
        uint32_t ad = aS + (uint32_t)(arow * AP + acol) * 4u;
        uint32_t bd = bS + (uint32_t)(brow * BP + bcol) * 4u;
#pragma unroll
        for (int it = 0; it < 4; it++)
            cpasync16(ad + it * 32 * AP * 4, Abase + (long)(32 * it) * K);
#pragma unroll
        for (int it = 0; it < 4; it++)
            cpasync16(bd + it * 8 * BP * 4, Wbase + (long)(8 * it) * N);
        cp_commit();
    }

    for (int itk = 0; itk < NIT; itk++) {
        int buf = itk & 1;
        // issue next tile into buf^1 (that buffer's last readers finished at
        // the trailing sync of iteration itk-1)
        if (itk + 1 < NIT) {
            int k0n = (itk + 1) * GBK;
            uint32_t ad = aS + (uint32_t)(((buf ^ 1) * GBM + arow) * AP + acol) * 4u;
            uint32_t bd = bS + (uint32_t)(((buf ^ 1) * GBK + brow) * BP + bcol) * 4u;
#pragma unroll
            for (int it = 0; it < 4; it++)
                cpasync16(ad + it * 32 * AP * 4, Abase + (long)(32 * it) * K + k0n);
#pragma unroll
            for (int it = 0; it < 4; it++)
                cpasync16(bd + it * 8 * BP * 4, Wbase + (long)(k0n + 8 * it) * N);
        }
        cp_commit();           // (empty group on last iter keeps counts uniform)
        cp_wait1();            // tile itk resident
        __syncthreads();

        const float* Ab = Asf + buf * GBM * AP;
        const float* Bb = Bsf + buf * GBK * BP;

#pragma unroll
        for (int ks = 0; ks < GBK; ks += 8) {
            uint32_t af[4][4], bf[4][2];
#pragma unroll
            for (int i = 0; i < 4; i++) {
                int m = wm0 + 16 * i;
                af[i][0] = f2tf32(Ab[(m + g)     * AP + ks + tg]);
                af[i][1] = f2tf32(Ab[(m + g + 8) * AP + ks + tg]);
                af[i][2] = f2tf32(Ab[(m + g)     * AP + ks + tg + 4]);
                af[i][3] = f2tf32(Ab[(m + g + 8) * AP + ks + tg + 4]);
            }
#pragma unroll
            for (int j = 0; j < 4; j++) {
                int n = wn0 + 8 * j;
                bf[j][0] = f2tf32(Bb[(ks + tg)     * BP + n + g]);
                bf[j][1] = f2tf32(Bb[(ks + tg + 4) * BP + n + g]);
            }
#pragma unroll
            for (int i = 0; i < 4; i++)
#pragma unroll
                for (int j = 0; j < 4; j++)
                    mma_tf32(acc[i][j], af[i][0], af[i][1], af[i][2], af[i][3],
                             bf[j][0], bf[j][1]);
        }
        __syncthreads();       // all warps done with buf -> may be overwritten
    }

    // Epilogue
#pragma unroll
    for (int i = 0; i < 4; i++) {
        int r = row0 + wm0 + 16 * i + g;
#pragma unroll
        for (int j = 0; j < 4; j++) {
            int c = col0 + wn0 + 8 * j + 2 * tg;
            float b0 = bias[c], b1 = bias[c + 1];
            float2 o0 = make_float2(acc[i][j][0] + b0, acc[i][j][1] + b1);
            float2 o1 = make_float2(acc[i][j][2] + b0, acc[i][j][3] + b1);
            *(float2*)&C[(long)r * N + c]       = o0;
            *(float2*)&C[(long)(r + 8) * N + c] = o1;
        }
    }
}

// ---------------------------------------------------------------------------
// TF32 tensor-core flash attention (unchanged from passing R9 kernel).
// ---------------------------------------------------------------------------
#define AQ 128
#define AK 64
#define QSTR 68
#define KSTR 68
#define VSTR 72
#define PSTR 68
#define ATT_SMEM ((AQ*QSTR + AK*KSTR + AK*VSTR + AQ*PSTR) * 4)

__global__ __launch_bounds__(256) void attn_tf32_kernel(
    const float* __restrict__ Qp, const float* __restrict__ Kp,
    const float* __restrict__ Vp, const int* __restrict__ mask,
    float* __restrict__ Ctx)
{
    extern __shared__ char smemraw[];
    uint32_t* Qs = (uint32_t*)smemraw;           // [AQ][QSTR] tf32
    uint32_t* Ks = Qs + AQ * QSTR;               // [AK][KSTR] tf32
    uint32_t* Vs = Ks + AK * KSTR;               // [AK][VSTR] tf32
    float*    Ps = (float*)(Vs + AK * VSTR);     // [AQ][PSTR] mask ints, then P tf32 bits
    uint32_t* Pu = (uint32_t*)Ps;

    int tid  = threadIdx.x;
    int lane = tid & 31, wid = tid >> 5;
    int g = lane >> 2, tg = lane & 3;
    int wm = wid * 16;
    int bh = blockIdx.y;
    int b = bh / HH, h = bh % HH;
    int q0 = blockIdx.x * AQ;

    int row0 = wm + g;
    int row1 = wm + g + 8;

    const float* Qbase = Qp + ((long)(b * LL + q0)) * DD + h * HDIM;
#pragma unroll
    for (int it = 0; it < 8; it++) {
        int s = tid + it * 256;
        int r = s >> 4, c4 = (s & 15) << 2;
        float4 qv = *(const float4*)(Qbase + (long)r * DD + c4);
        Qs[r * QSTR + c4 + 0] = f2tf32(qv.x * 0.125f);
        Qs[r * QSTR + c4 + 1] = f2tf32(qv.y * 0.125f);
        Qs[r * QSTR + c4 + 2] = f2tf32(qv.z * 0.125f);
        Qs[r * QSTR + c4 + 3] = f2tf32(qv.w * 0.125f);
    }

    float Of[8][4];
#pragma unroll
    for (int j = 0; j < 8; j++)
#pragma unroll
        for (int c = 0; c < 4; c++) Of[j][c] = 0.f;
    float m0 = -1e30f, m1 = -1e30f, l0 = 0.f, l1 = 0.f;

    const float* Kb = Kp + ((long)(b * LL)) * DD + h * HDIM;
    const float* Vb = Vp + ((long)(b * LL)) * DD + h * HDIM;
    const int*   Mb = mask + (long)b * LL * LL + (long)q0 * LL;

    for (int kt = 0; kt < LL; kt += AK) {
        __syncthreads();

#pragma unroll
        for (int it = 0; it < 4; it++) {
            int s = tid + it * 256;
            int r = s >> 4, c4 = (s & 15) << 2;
            float4 kv = *(const float4*)(Kb + (long)(kt + r) * DD + c4);
            Ks[r * KSTR + c4 + 0] = f2tf32(kv.x);
            Ks[r * KSTR + c4 + 1] = f2tf32(kv.y);
            Ks[r * KSTR + c4 + 2] = f2tf32(kv.z);
            Ks[r * KSTR + c4 + 3] = f2tf32(kv.w);
            float4 vv = *(const float4*)(Vb + (long)(kt + r) * DD + c4);
            Vs[r * VSTR + c4 + 0] = f2tf32(vv.x);
            Vs[r * VSTR + c4 + 1] = f2tf32(vv.y);
            Vs[r * VSTR + c4 + 2] = f2tf32(vv.z);
            Vs[r * VSTR + c4 + 3] = f2tf32(vv.w);
        }
#pragma unroll
        for (int it = 0; it < 8; it++) {
            int s = tid + it * 256;
            int r = s >> 4, c4 = (s & 15) << 2;
            int4 mv = *(const int4*)(Mb + (long)r * LL + kt + c4);
            *(int4*)&Ps[r * PSTR + c4] = mv;
        }
        __syncthreads();

        float sf[8][4];
#pragma unroll
        for (int j = 0; j < 8; j++)
#pragma unroll
            for (int c = 0; c < 4; c++) sf[j][c] = 0.f;

#pragma unroll
        for (int ks = 0; ks < AK; ks += 8) {
            uint32_t a0 = Qs[row0 * QSTR + ks + tg];
            uint32_t a1 = Qs[row1 * QSTR + ks + tg];
            uint32_t a2 = Qs[row0 * QSTR + ks + tg + 4];
            uint32_t a3 = Qs[row1 * QSTR + ks + tg + 4];
#pragma unroll
            for (int j = 0; j < 8; j++) {
                uint32_t b0 = Ks[(8 * j + g) * KSTR + ks + tg];
                uint32_t b1 = Ks[(8 * j + g) * KSTR + ks + tg + 4];
                mma_tf32(sf[j], a0, a1, a2, a3, b0, b1);
            }
        }

        float mx0 = -1e30f, mx1 = -1e30f;
#pragma unroll
        for (int j = 0; j < 8; j++) {
            int cb = 8 * j + 2 * tg;
            int2 mv0 = *(const int2*)&Ps[row0 * PSTR + cb];
            int2 mv1 = *(const int2*)&Ps[row1 * PSTR + cb];
            sf[j][0] = mv0.x ? sf[j][0] : -1e30f;
            sf[j][1] = mv0.y ? sf[j][1] : -1e30f;
            sf[j][2] = mv1.x ? sf[j][2] : -1e30f;
            sf[j][3] = mv1.y ? sf[j][3] : -1e30f;
            mx0 = fmaxf(mx0, fmaxf(sf[j][0], sf[j][1]));
            mx1 = fmaxf(mx1, fmaxf(sf[j][2], sf[j][3]));
        }
        mx0 = fmaxf(mx0, __shfl_xor_sync(0xffffffffu, mx0, 1));
        mx0 = fmaxf(mx0, __shfl_xor_sync(0xffffffffu, mx0, 2));
        mx1 = fmaxf(mx1, __shfl_xor_sync(0xffffffffu, mx1, 1));
        mx1 = fmaxf(mx1, __shfl_xor_sync(0xffffffffu, mx1, 2));

        float mn0 = fmaxf(m0, mx0), mn1 = fmaxf(m1, mx1);
        float cr0 = __expf(m0 - mn0), cr1 = __expf(m1 - mn1);
        m0 = mn0; m1 = mn1;

        float ls0 = 0.f, ls1 = 0.f;
#pragma unroll
        for (int j = 0; j < 8; j++) {
            float p0 = __expf(sf[j][0] - mn0);
            float p1 = __expf(sf[j][1] - mn0);
            float p2 = __expf(sf[j][2] - mn1);
            float p3 = __expf(sf[j][3] - mn1);
            ls0 += p0 + p1;
            ls1 += p2 + p3;
            int cb = 8 * j + 2 * tg;
            *(uint2*)&Pu[row0 * PSTR + cb] = make_uint2(f2tf32(p0), f2tf32(p1));
            *(uint2*)&Pu[row1 * PSTR + cb] = make_uint2(f2tf32(p2), f2tf32(p3));
        }
        ls0 += __shfl_xor_sync(0xffffffffu, ls0, 1);
        ls0 += __shfl_xor_sync(0xffffffffu, ls0, 2);
        ls1 += __shfl_xor_sync(0xffffffffu, ls1, 1);
        ls1 += __shfl_xor_sync(0xffffffffu, ls1, 2);
        l0 = l0 * cr0 + ls0;
        l1 = l1 * cr1 + ls1;
#pragma unroll
        for (int j = 0; j < 8; j++) {
            Of[j][0] *= cr0; Of[j][1] *= cr0;
            Of[j][2] *= cr1; Of[j][3] *= cr1;
        }
        __syncthreads();

#pragma unroll
        for (int ks = 0; ks < AK; ks += 8) {
            uint32_t a0 = Pu[row0 * PSTR + ks + tg];
            uint32_t a1 = Pu[row1 * PSTR + ks + tg];
            uint32_t a2 = Pu[row0 * PSTR + ks + tg + 4];
            uint32_t a3 = Pu[row1 * PSTR + ks + tg + 4];
#pragma unroll
            for (int j = 0; j < 8; j++) {
                uint32_t b0 = Vs[(ks + tg)     * VSTR + 8 * j + g];
                uint32_t b1 = Vs[(ks + tg + 4) * VSTR + 8 * j + g];
                mma_tf32(Of[j], a0, a1, a2, a3, b0, b1);
            }
        }
    }

    float inv0 = 1.f / l0, inv1 = 1.f / l1;
    float* Ob = Ctx + ((long)(b * LL + q0)) * DD + h * HDIM;
#pragma unroll
    for (int j = 0; j < 8; j++) {
        int c = 8 * j + 2 * tg;
        *(float2*)&Ob[(long)row0 * DD + c] =
            make_float2(Of[j][0] * inv0, Of[j][1] * inv0);
        *(float2*)&Ob[(long)row1 * DD + c] =
            make_float2(Of[j][2] * inv1, Of[j][3] * inv1);
    }
}

// ---------------------------------------------------------------------------
extern "C" void kernel_launch(void* const* d_in, const int* in_sizes, int n_in,
                              void* d_out, int out_size)
{
    const float* q    = (const float*)d_in[0];
    const float* k    = (const float*)d_in[1];
    const float* v    = (const float*)d_in[2];
    const int*   mask = (const int*)  d_in[3];
    const float* WQ   = (const float*)d_in[4];
    const float* bQ   = (const float*)d_in[5];
    const float* WK   = (const float*)d_in[6];
    const float* bK   = (const float*)d_in[7];
    const float* WV   = (const float*)d_in[8];
    const float* bV   = (const float*)d_in[9];
    const float* WO   = (const float*)d_in[10];
    const float* bO   = (const float*)d_in[11];
    float* out = (float*)d_out;

    float *gQ, *gK, *gV, *gC;
    cudaGetSymbolAddress((void**)&gQ, g_Q);
    cudaGetSymbolAddress((void**)&gK, g_K);
    cudaGetSymbolAddress((void**)&gV, g_V);
    cudaGetSymbolAddress((void**)&gC, g_C);

    static int attr_set = 0;
    if (!attr_set) {
        cudaFuncSetAttribute(sgemm_tf32_pipe_kernel,
                             cudaFuncAttributeMaxDynamicSharedMemorySize, GSMEM);
        cudaFuncSetAttribute(attn_tf32_kernel,
                             cudaFuncAttributeMaxDynamicSharedMemorySize, ATT_SMEM);
        attr_set = 1;
    }

    const int M = BB * LL;  // 8192

    GemmArgs gq = {q, WQ, bQ, gQ};
    GemmArgs gk = {k, WK, bK, gK};
    GemmArgs gv = {v, WV, bV, gV};

    // QKV projections fused into one launch (z batches the 3 GEMMs)
    sgemm_tf32_pipe_kernel<<<dim3(DD / GBN, M / GBM, 3), 256, GSMEM>>>(
        gq, gk, gv, M, DD, DD);

    attn_tf32_kernel<<<dim3(LL / AQ, BB * HH), 256, ATT_SMEM>>>(
        gQ, gK, gV, mask, gC);

    GemmArgs go = {gC, WO, bO, out};
    sgemm_tf32_pipe_kernel<<<dim3(DD / GBN, M / GBM, 1), 256, GSMEM>>>(
        go, go, go, M, DD, DD);
}